// round 17
// baseline (speedup 1.0000x reference)
#include <cuda_runtime.h>
#include <cuda_bf16.h>
#include <cstdint>

#define D_VEC 8              // 32 floats = 8 float4 per node row
#define N_MAX 102400         // max nodes supported by scratch
#define CAP 88               // records per node (mean 32 + ~10 sigma; 8 | CAP)

// Scratch (module-static; allocation-free at runtime). ~72MB records.
__device__ int2 g_rec[(size_t)N_MAX * CAP + 8];
__device__ int  g_cnt[N_MAX];

__global__ void zero_cnt_kernel(int n) {
    int i = blockIdx.x * blockDim.x + threadIdx.x;
    if (i < n) g_cnt[i] = 0;
}

__global__ void zero_out_kernel(float4* __restrict__ out, int n4) {
    int i = blockIdx.x * blockDim.x + threadIdx.x;
    if (i < n4) out[i] = make_float4(0.f, 0.f, 0.f, 0.f);
}

__device__ __forceinline__ void red_v4(float4* addr, float4 r) {
    asm volatile("red.global.add.v4.f32 [%0], {%1, %2, %3, %4};"
                 :: "l"(addr), "f"(r.x), "f"(r.y), "f"(r.z), "f"(r.w)
                 : "memory");
}

// Phase A: bin edges by TARGET NODE. 4 edges/thread, fully-coalesced 16B
// metadata loads, 4 independent counter atomics + 4 record stores in flight.
// Overflow (pos >= CAP) is ONLY counted — the accum kernel's slow path
// recomputes such nodes exactly, so bin never touches `out`/`input`.
__global__ void __launch_bounds__(256)
bin_kernel(const int4*   __restrict__ sidx4,
           const int4*   __restrict__ tidx4,
           const float4* __restrict__ enorm4,
           const float4* __restrict__ esgn4,
           int n_quads) {
    int q = blockIdx.x * blockDim.x + threadIdx.x;
    if (q >= n_quads) return;

    int4   s4 = __ldg(sidx4  + q);
    int4   t4 = __ldg(tidx4  + q);
    float4 en = __ldg(enorm4 + q);
    float4 eg = __ldg(esgn4  + q);

    int   ss[4] = {s4.x, s4.y, s4.z, s4.w};
    int   tt[4] = {t4.x, t4.y, t4.z, t4.w};
    float ww[4] = {en.x * eg.x, en.y * eg.y, en.z * eg.z, en.w * eg.w};

    int pos[4];
#pragma unroll
    for (int i = 0; i < 4; i++)
        pos[i] = atomicAdd(&g_cnt[tt[i]], 1);   // 4 independent chains

#pragma unroll
    for (int i = 0; i < 4; i++) {
        if (pos[i] < CAP)
            g_rec[(size_t)tt[i] * CAP + pos[i]] =
                make_int2(ss[i], __float_as_int(ww[i]));
        // else: counted only; accum slow path recomputes this node.
    }
}

// Phase B: one 8-lane group per NODE, register accumulator, zero SMEM,
// zero atomics. 8 records per iteration (4 prefetched int4 record loads +
// 8 independent gathers in flight). Every node is written exactly once by
// a plain STG.128 -> no output pre-zeroing needed anywhere.
__global__ void __launch_bounds__(256, 2)
node_accum_kernel(const float4* __restrict__ input,
                  float4* __restrict__ out,
                  const int*   __restrict__ sidx,
                  const int*   __restrict__ tidx,
                  const float* __restrict__ enorm,
                  const float* __restrict__ esgn,
                  int n_nodes, int n_edges) {
    int gid  = blockIdx.x * blockDim.x + threadIdx.x;
    int node = gid >> 3;
    int j    = gid & 7;
    if (node >= n_nodes) return;

    int raw = __ldg(&g_cnt[node]);
    float4 acc = make_float4(0.f, 0.f, 0.f, 0.f);

    if (raw <= CAP) {
        int cnt = raw;
        const int2* base = g_rec + (size_t)node * CAP;

        int4 r0 = make_int4(0,0,0,0), r1 = r0, r2 = r0, r3 = r0;
        if (cnt > 0) {
            r0 = __ldcg((const int4*)(base + 0));
            r1 = __ldcg((const int4*)(base + 2));
            r2 = __ldcg((const int4*)(base + 4));
            r3 = __ldcg((const int4*)(base + 6));
        }

        for (int k = 0; k < cnt; k += 8) {
            // Prefetch next window under this window's gathers.
            int4 n0 = r0, n1 = r1, n2 = r2, n3 = r3;
            if (k + 8 < cnt) {
                const int2* nb = base + k + 8;
                n0 = __ldcg((const int4*)(nb + 0));
                n1 = __ldcg((const int4*)(nb + 2));
                n2 = __ldcg((const int4*)(nb + 4));
                n3 = __ldcg((const int4*)(nb + 6));
            }

            int raw_s[8] = {r0.x, r0.z, r1.x, r1.z, r2.x, r2.z, r3.x, r3.z};
            int raw_w[8] = {r0.y, r0.w, r1.y, r1.w, r2.y, r2.w, r3.y, r3.w};

            int   rs[8];
            float rw[8];
#pragma unroll
            for (int i = 0; i < 8; i++) {
                bool valid = (k + i < cnt);
                rs[i] = valid ? raw_s[i] : 0;
                rw[i] = valid ? __int_as_float(raw_w[i]) : 0.f;
            }

            // 8 independent gathers in flight.
            float4 g[8];
#pragma unroll
            for (int i = 0; i < 8; i++)
                g[i] = __ldcg(input + (size_t)rs[i] * D_VEC + j);

#pragma unroll
            for (int i = 0; i < 8; i++) {
                acc.x += g[i].x * rw[i]; acc.y += g[i].y * rw[i];
                acc.z += g[i].z * rw[i]; acc.w += g[i].w * rw[i];
            }

            r0 = n0; r1 = n1; r2 = n2; r3 = n3;
        }
    } else {
        // Overflow (statistically never for benchmark shapes): exact slow
        // path — scan the whole edge list for this target. Correct always.
        for (int e = 0; e < n_edges; e++) {
            if (__ldg(tidx + e) == node) {
                int   s = __ldg(sidx + e);
                float w = __ldg(esgn + e) * __ldg(enorm + e);
                float4 v = __ldcg(input + (size_t)s * D_VEC + j);
                acc.x += v.x * w; acc.y += v.y * w;
                acc.z += v.z * w; acc.w += v.w * w;
            }
        }
    }

    out[(size_t)node * D_VEC + j] = acc;   // sole writer: plain STG.128
}

// Direct-atomic kernel (fallback for unexpected shapes).
__global__ void __launch_bounds__(256)
legacy_kernel(const float4* __restrict__ input,
              const int* __restrict__ sidx,
              const int* __restrict__ tidx,
              const float* __restrict__ enorm,
              const float* __restrict__ esgn,
              float4* __restrict__ out,
              int n_edges) {
    int gid = blockIdx.x * blockDim.x + threadIdx.x;
    int e = gid >> 3;
    int j = gid & 7;
    if (e >= n_edges) return;
    int   s = __ldg(sidx + e);
    int   t = __ldg(tidx + e);
    float w = __ldg(esgn + e) * __ldg(enorm + e);
    float4 v = __ldg(input + (size_t)s * D_VEC + j);
    float4 r;
    r.x = v.x * w; r.y = v.y * w; r.z = v.z * w; r.w = v.w * w;
    red_v4(out + (size_t)t * D_VEC + j, r);
}

extern "C" void kernel_launch(void* const* d_in, const int* in_sizes, int n_in,
                              void* d_out, int out_size) {
    const float4* input = (const float4*)d_in[0];   // [n_nodes, 32] fp32
    const int*    eidx  = (const int*)d_in[1];      // [2, n_edges] int32
    const float*  enorm = (const float*)d_in[2];    // [n_edges]
    const float*  esgn  = (const float*)d_in[3];    // [n_edges]
    float4*       out   = (float4*)d_out;           // [n_nodes, 32] fp32

    int n_edges = in_sizes[2];
    int n_nodes = in_sizes[0] / 32;
    const int* sidx = eidx;
    const int* tidx = eidx + n_edges;

    if (n_nodes <= N_MAX && (n_edges & 3) == 0) {
        zero_cnt_kernel<<<(n_nodes + 255) / 256, 256>>>(n_nodes);

        int n_quads = n_edges >> 2;
        bin_kernel<<<(n_quads + 255) / 256, 256>>>(
            (const int4*)sidx, (const int4*)tidx,
            (const float4*)enorm, (const float4*)esgn, n_quads);

        long long total_threads = (long long)n_nodes * D_VEC;
        int blocks = (int)((total_threads + 255) / 256);
        node_accum_kernel<<<blocks, 256>>>(
            input, out, sidx, tidx, enorm, esgn, n_nodes, n_edges);
    } else {
        int n4 = out_size / 4;
        zero_out_kernel<<<(n4 + 255) / 256, 256>>>(out, n4);
        legacy_kernel<<<(int)(((long long)n_edges * D_VEC + 255) / 256), 256>>>(
            input, sidx, tidx, enorm, esgn, out, n_edges);
    }
}